// round 6
// baseline (speedup 1.0000x reference)
#include <cuda_runtime.h>
#include <cuda_bf16.h>

// ---------------- problem constants ----------------
#define N_NODES 20000
#define N_EDGES 160000
#define MEGA_NB 64
#define PERS_NB 148

// ---------------- device scratch (static; no allocs) ----------------
__device__ __align__(16) float g_P[N_NODES * 320];   // P[n, s, o] (max 8*40 cols)
__device__ __align__(16) float g_R[N_NODES * 40];    // R[n, o]
__device__ __align__(16) float g_AGG1[N_NODES * 40];
__device__ __align__(16) float g_AGG2[N_NODES * 24];
__device__ __align__(16) float g_AGG3[N_NODES * 24];
__device__ int   g_deg[N_NODES];
__device__ int   g_cursor[N_NODES];
__device__ int   g_bsum[PERS_NB];
__device__ __align__(8)  int2   g_srt[N_EDGES];        // (src, tgt) sorted by src
__device__ __align__(16) float4 g_eperm[N_EDGES * 2];  // e payload, src-sorted
__device__ float g_poolpart[MEGA_NB * 24];
__device__ __align__(16) float g_v1[256];
__device__ __align__(16) float g_v2[768];
__device__ __align__(16) float g_v3[512];
__device__ float g_v3r[64];
__device__ unsigned g_barA;    // k_big barrier counter
__device__ unsigned g_barB;    // k_mid barrier counter
__device__ unsigned g_barcnt;  // k_mega barrier counter

// ---------------- helpers ----------------
__device__ __forceinline__ void ffma2(unsigned long long& d, unsigned long long a,
                                      unsigned long long b) {
    asm("fma.rn.f32x2 %0, %1, %2, %0;" : "+l"(d) : "l"(a), "l"(b));
}
__device__ __forceinline__ unsigned long long packf2(float x) {
    unsigned long long r;
    asm("mov.b64 %0, {%1, %1};" : "=l"(r) : "f"(x));
    return r;
}
__device__ __forceinline__ float2 unpackf2(unsigned long long v) {
    float2 f;
    asm("mov.b64 {%0, %1}, %2;" : "=f"(f.x), "=f"(f.y) : "l"(v));
    return f;
}
// grid barrier: nb blocks, all resident. cnt must start 0 at kernel entry.
__device__ __forceinline__ void gridbar(unsigned* cnt, int& epoch, int nb) {
    __threadfence();
    __syncthreads();
    epoch++;
    if (threadIdx.x == 0) {
        atomicAdd(cnt, 1u);
        unsigned target = (unsigned)epoch * (unsigned)nb;
        while (*((volatile unsigned*)cnt) < target) __nanosleep(20);
    }
    __syncthreads();
}

// ---------------- shared edge phase ----------------
// 2 thread-slots per edge (column halves). AGG[tgt] += R[src] + sum_s e*P[src].
template <int FO>
__device__ __forceinline__ void edge_phase(float* __restrict__ AGG,
                                           int start, int stride)
{
    constexpr int FO4 = FO / 4;
    constexpr int HALF = FO4 / 2;
    for (int gid = start; gid < 2 * N_EDGES; gid += stride) {
        int edge = gid >> 1;
        int h = gid & 1;
        int2 st = g_srt[edge];
        float4 ea = g_eperm[2 * edge];
        float4 eb = g_eperm[2 * edge + 1];
        const float4* P = reinterpret_cast<const float4*>(g_P)
                          + (size_t)st.x * (8 * FO4) + h * HALF;
        const float4* R = reinterpret_cast<const float4*>(g_R)
                          + (size_t)st.x * FO4 + h * HALF;
        float* dst = AGG + (size_t)st.y * FO + h * HALF * 4;
#pragma unroll
        for (int c = 0; c < HALF; c++) {
            float4 m = R[c];
            float4 p;
#define ACC_TERM(ES, SI) { p = P[(SI) * FO4 + c]; \
            m.x += (ES) * p.x; m.y += (ES) * p.y; m.z += (ES) * p.z; m.w += (ES) * p.w; }
            ACC_TERM(ea.x, 0) ACC_TERM(ea.y, 1) ACC_TERM(ea.z, 2) ACC_TERM(ea.w, 3)
            ACC_TERM(eb.x, 4) ACC_TERM(eb.y, 5) ACC_TERM(eb.z, 6) ACC_TERM(eb.w, 7)
#undef ACC_TERM
            asm volatile("red.global.add.v4.f32 [%0], {%1,%2,%3,%4};"
                         :: "l"(dst + c * 4), "f"(m.x), "f"(m.y), "f"(m.z), "f"(m.w)
                         : "memory");
        }
    }
}

// ---------------- node1 kernel (also zeroes CSR state) ----------------
// grid (79 node-tiles, 5 col-chunks) x 256; cols: [0,320) P, [320,360) R, [360,400) AGG
__global__ __launch_bounds__(256) void k_node1(
    const float* __restrict__ xin,
    const float* __restrict__ We, const float* __restrict__ be,
    const float* __restrict__ root, const float* __restrict__ bias)
{
    constexpr int FI = 16, FO = 40, CC = 5;
    constexpr int CC16 = CC * 16;
    __shared__ __align__(16) float Wsh[FI * CC16];
    __shared__ float bsh[FO];
    int t = threadIdx.x;
    int cg0 = blockIdx.y * CC;
    int colbase = cg0 * 16;

    if (blockIdx.y == 0) {
        int n = blockIdx.x * 256 + t;
        if (n < N_NODES) g_deg[n] = 0;
        if (blockIdx.x == 0 && t == 0) { g_barA = 0u; g_barB = 0u; g_barcnt = 0u; }
    }

    for (int idx = t; idx < FI * CC16; idx += 256) {
        int f = idx / CC16, cl = idx % CC16;
        int c = colbase + cl;
        float w;
        if (c < 8 * FO) {
            int s = c / FO, o = c % FO;
            w = We[s * (FI * FO) + f * FO + o];
        } else if (c < 9 * FO) {
            int o = c - 8 * FO;
            w = be[f * FO + o];
        } else {
            int o = c - 9 * FO;
            w = root[f * FO + o];
        }
        Wsh[idx] = w;
    }
    for (int idx = t; idx < FO; idx += 256) bsh[idx] = bias[idx];
    __syncthreads();

    int node = blockIdx.x * 256 + t;
    if (node >= N_NODES) return;

    float h[FI];
    const float4* hv = reinterpret_cast<const float4*>(xin + (size_t)node * FI);
#pragma unroll
    for (int f4 = 0; f4 < FI / 4; f4++) {
        float4 a = hv[f4];
        h[4*f4+0]=a.x; h[4*f4+1]=a.y; h[4*f4+2]=a.z; h[4*f4+3]=a.w;
    }

    const ulonglong2* Wv = reinterpret_cast<const ulonglong2*>(Wsh);
    float4* Pv = reinterpret_cast<float4*>(g_P) + (size_t)node * (8 * FO / 4);
    float4* Rv = reinterpret_cast<float4*>(g_R) + (size_t)node * (FO / 4);
    float4* Av = reinterpret_cast<float4*>(g_AGG1) + (size_t)node * (FO / 4);

#pragma unroll
    for (int cg = 0; cg < CC; cg++) {
        unsigned long long acc[8];
#pragma unroll
        for (int k = 0; k < 8; k++) acc[k] = 0ull;
#pragma unroll
        for (int f = 0; f < FI; f++) {
            const ulonglong2* wrow = Wv + f * (CC * 4) + cg * 4;
            ulonglong2 wA = wrow[0], wB = wrow[1], wC = wrow[2], wD = wrow[3];
            unsigned long long ha = packf2(h[f]);
            ffma2(acc[0], ha, wA.x); ffma2(acc[1], ha, wA.y);
            ffma2(acc[2], ha, wB.x); ffma2(acc[3], ha, wB.y);
            ffma2(acc[4], ha, wC.x); ffma2(acc[5], ha, wC.y);
            ffma2(acc[6], ha, wD.x); ffma2(acc[7], ha, wD.y);
        }
#pragma unroll
        for (int q = 0; q < 4; q++) {
            int cb = (cg0 + cg) * 16 + q * 4;
            float2 a0 = unpackf2(acc[2*q]), a1 = unpackf2(acc[2*q+1]);
            float4 va = make_float4(a0.x, a0.y, a1.x, a1.y);
            if (cb < 8 * FO) {
                Pv[cb / 4] = va;
            } else if (cb < 9 * FO) {
                Rv[(cb - 8 * FO) / 4] = va;
            } else {
                int o = cb - 9 * FO;
                va.x += bsh[o]; va.y += bsh[o+1]; va.z += bsh[o+2]; va.w += bsh[o+3];
                Av[o / 4] = va;
            }
        }
    }
}

// ---------------- shared node phase (FO=24) for layers 2/3 ----------------
// item = node*3 + chunk; chunk covers 80 cols (5 groups of 16). COLS=240.
// weights already staged in Wsh (FI x 240) + bs[24].
template <int FI>
__device__ __forceinline__ void node_phase24(
    const float* __restrict__ hin, float* __restrict__ AGG,
    const float* __restrict__ Wsh, const float* __restrict__ bs, int item)
{
    constexpr int FO = 24;
    int node = item / 3;
    int chunk = item % 3;
    int cg0 = chunk * 5;

    float h[FI];
    const float4* hv = reinterpret_cast<const float4*>(hin + (size_t)node * FI);
#pragma unroll
    for (int f4 = 0; f4 < FI / 4; f4++) {
        float4 a = hv[f4];
        a.x = fmaxf(a.x, 0.f); a.y = fmaxf(a.y, 0.f);
        a.z = fmaxf(a.z, 0.f); a.w = fmaxf(a.w, 0.f);
        h[4*f4+0]=a.x; h[4*f4+1]=a.y; h[4*f4+2]=a.z; h[4*f4+3]=a.w;
    }

    const ulonglong2* Wv = reinterpret_cast<const ulonglong2*>(Wsh);
    float4* Pv = reinterpret_cast<float4*>(g_P) + (size_t)node * 48;
    float4* Rv = reinterpret_cast<float4*>(g_R) + (size_t)node * 6;
    float4* Av = reinterpret_cast<float4*>(AGG) + (size_t)node * 6;

#pragma unroll
    for (int cg = 0; cg < 5; cg++) {
        unsigned long long acc[8];
#pragma unroll
        for (int k = 0; k < 8; k++) acc[k] = 0ull;
#pragma unroll
        for (int f = 0; f < FI; f++) {
            const ulonglong2* wrow = Wv + f * 60 + (cg0 + cg) * 4;
            ulonglong2 wA = wrow[0], wB = wrow[1], wC = wrow[2], wD = wrow[3];
            unsigned long long ha = packf2(h[f]);
            ffma2(acc[0], ha, wA.x); ffma2(acc[1], ha, wA.y);
            ffma2(acc[2], ha, wB.x); ffma2(acc[3], ha, wB.y);
            ffma2(acc[4], ha, wC.x); ffma2(acc[5], ha, wC.y);
            ffma2(acc[6], ha, wD.x); ffma2(acc[7], ha, wD.y);
        }
#pragma unroll
        for (int q = 0; q < 4; q++) {
            int cb = (cg0 + cg) * 16 + q * 4;
            float2 a0 = unpackf2(acc[2*q]), a1 = unpackf2(acc[2*q+1]);
            float4 va = make_float4(a0.x, a0.y, a1.x, a1.y);
            if (cb < 8 * FO) {
                Pv[cb / 4] = va;
            } else if (cb < 9 * FO) {
                Rv[(cb - 8 * FO) / 4] = va;
            } else {
                int o = cb - 9 * FO;
                va.x += bs[o]; va.y += bs[o+1]; va.z += bs[o+2]; va.w += bs[o+3];
                Av[o / 4] = va;
            }
        }
    }
}

// ---------------- k_big: CSR build + edge layer 1 (148 x 1024, persistent) ----------------
__global__ __launch_bounds__(1024, 1) void k_big(
    const int2* __restrict__ ei, const float4* __restrict__ e4)
{
    __shared__ int wsum[32];
    __shared__ int sbase;
    int t = threadIdx.x;
    int b = blockIdx.x;
    int lane = t & 31, w = t >> 5;
    const int NT = PERS_NB * 1024;
    int epoch = 0;

    // phase 1: histogram
    for (int i = b * 1024 + t; i < N_EDGES; i += NT)
        atomicAdd(&g_deg[ei[i].x], 1);
    gridbar(&g_barA, epoch, PERS_NB);

    // phase 2a: per-block degree sums (chunk of 136 nodes per block)
    int nbase = b * 136;
    int cnt = N_NODES - nbase; if (cnt > 136) cnt = 136; if (cnt < 0) cnt = 0;
    int d = (t < cnt) ? g_deg[nbase + t] : 0;
    {
        int s = d;
#pragma unroll
        for (int off = 16; off >= 1; off >>= 1)
            s += __shfl_down_sync(0xffffffffu, s, off);
        if (lane == 0) wsum[w] = s;
        __syncthreads();
        if (w == 0) {
            int v = wsum[lane];
#pragma unroll
            for (int off = 16; off >= 1; off >>= 1)
                v += __shfl_down_sync(0xffffffffu, v, off);
            if (lane == 0) g_bsum[b] = v;
        }
    }
    gridbar(&g_barA, epoch, PERS_NB);

    // phase 2b: block prefix + local exclusive scan -> g_cursor
    if (w == 0) {
        int partial = 0;
        for (int i = lane; i < b; i += 32) partial += g_bsum[i];
#pragma unroll
        for (int off = 16; off >= 1; off >>= 1)
            partial += __shfl_down_sync(0xffffffffu, partial, off);
        if (lane == 0) sbase = partial;
    }
    // local inclusive scan of d over the block
    int sc = d;
#pragma unroll
    for (int off = 1; off < 32; off <<= 1) {
        int n = __shfl_up_sync(0xffffffffu, sc, off);
        if (lane >= off) sc += n;
    }
    if (lane == 31) wsum[w] = sc;
    __syncthreads();
    int woff = 0;
    for (int i = 0; i < w; i++) woff += wsum[i];  // w < 5 relevant (d=0 beyond)
    if (t < cnt) g_cursor[nbase + t] = sbase + woff + sc - d;
    gridbar(&g_barA, epoch, PERS_NB);

    // phase 3: scatter
    for (int i = b * 1024 + t; i < N_EDGES; i += NT) {
        int2 st = ei[i];
        float4 pa = e4[2 * i], pb = e4[2 * i + 1];
        int p = atomicAdd(&g_cursor[st.x], 1);
        g_srt[p] = st;
        g_eperm[2 * p] = pa;
        g_eperm[2 * p + 1] = pb;
    }
    gridbar(&g_barA, epoch, PERS_NB);

    // phase 4: edge layer 1 (P/R from k_node1, stream-ordered)
    edge_phase<40>(g_AGG1, b * 1024 + t, NT);
}

// ---------------- k_mid: node2 + edge2 + node3 + edge3 (148 x 768, persistent) ----------------
__global__ __launch_bounds__(768, 1) void k_mid(
    const float* __restrict__ We2, const float* __restrict__ be2,
    const float* __restrict__ root2, const float* __restrict__ b2,
    const float* __restrict__ We3, const float* __restrict__ be3,
    const float* __restrict__ root3, const float* __restrict__ b3)
{
    __shared__ __align__(16) float Wsh[40 * 240];   // max(FI2,FI3) x 240
    __shared__ float bs2[24], bs3[24];
    int t = threadIdx.x;
    int b = blockIdx.x;
    const int NT = PERS_NB * 768;
    int epoch = 0;

    // stage layer-2 weights (inputs; AGG1 ready via stream order)
    for (int idx = t; idx < 40 * 240; idx += 768) {
        int f = idx / 240, c = idx % 240;
        float wv;
        if (c < 192)      wv = We2[(c / 24) * (40 * 24) + f * 24 + (c % 24)];
        else if (c < 216) wv = be2[f * 24 + (c - 192)];
        else              wv = root2[f * 24 + (c - 216)];
        Wsh[idx] = wv;
    }
    if (t < 24) bs2[t] = b2[t];
    __syncthreads();

    // node2: items 20000*3
    {
        int item = b * 768 + t;
        if (item < N_NODES * 3)
            node_phase24<40>(g_AGG1, g_AGG2, Wsh, bs2, item);
    }
    gridbar(&g_barB, epoch, PERS_NB);

    // stage layer-3 weights (Wsh reuse; local block done with it)
    for (int idx = t; idx < 24 * 240; idx += 768) {
        int f = idx / 240, c = idx % 240;
        float wv;
        if (c < 192)      wv = We3[(c / 24) * (24 * 24) + f * 24 + (c % 24)];
        else if (c < 216) wv = be3[f * 24 + (c - 192)];
        else              wv = root3[f * 24 + (c - 216)];
        Wsh[idx] = wv;
    }
    if (t < 24) bs3[t] = b3[t];

    // edge2 (doesn't touch Wsh)
    edge_phase<24>(g_AGG2, b * 768 + t, NT);
    gridbar(&g_barB, epoch, PERS_NB);

    // node3
    {
        int item = b * 768 + t;
        if (item < N_NODES * 3)
            node_phase24<24>(g_AGG2, g_AGG3, Wsh, bs3, item);
    }
    gridbar(&g_barB, epoch, PERS_NB);

    // edge3
    edge_phase<24>(g_AGG3, b * 768 + t, NT);
}

// ---------------- mega kernel: pool + whole MLP (64 x 256) ----------------
__global__ __launch_bounds__(256) void k_mega(
    const float* __restrict__ Wd1, const float* __restrict__ bd1,
    const float* __restrict__ Wd2, const float* __restrict__ bd2,
    const float* __restrict__ Wd3, const float* __restrict__ bd3,
    const float* __restrict__ Wd4, const float* __restrict__ bd4,
    const float* __restrict__ Wd5, const float* __restrict__ bd5,
    const float* __restrict__ Wd6, const float* __restrict__ bd6,
    float* __restrict__ out)
{
    __shared__ float w3s[256 * 12];
    __shared__ float w4s[768 * 8];
    __shared__ float w5s[512];
    __shared__ float a2[256];
    __shared__ float a3[768];
    __shared__ float v0[24];
    __shared__ float a1[96];
    __shared__ float poolacc[10][24];
    __shared__ float bd3s[12], bd4s[8];
    __shared__ float red8[8];

    int t = threadIdx.x;
    int b = blockIdx.x;
    int epoch = 0;

    for (int idx = t; idx < 256 * 12; idx += 256) {
        int i = idx / 12, j = idx % 12;
        w3s[idx] = Wd3[i * 768 + b * 12 + j];
    }
    for (int idx = t; idx < 768 * 8; idx += 256) {
        int i = idx / 8, j = idx % 8;
        w4s[idx] = Wd4[i * 512 + b * 8 + j];
    }
    for (int idx = t; idx < 512; idx += 256) w5s[idx] = Wd5[idx * 64 + b];
    if (t < 12) bd3s[t] = bd3[b * 12 + t];
    if (t < 8)  bd4s[t] = bd4[b * 8 + t];
    float bd5b = bd5[b];
    float wd6b = Wd6[b];

    // phase P: pool partials
    {
        int c = t % 24, slot = t / 24;
        float local = 0.0f;
        if (slot < 10) {
            for (int r = b * 10 + slot; r < N_NODES; r += MEGA_NB * 10)
                local += fmaxf(__ldcg(&g_AGG3[r * 24 + c]), 0.0f);
            poolacc[slot][c] = local;
        }
        __syncthreads();
        if (t < 24) {
            float s = 0.0f;
#pragma unroll
            for (int k = 0; k < 10; k++) s += poolacc[k][t];
            g_poolpart[b * 24 + t] = s;
        }
    }
    gridbar(&g_barcnt, epoch, MEGA_NB);   // 1

    // phase A: block 0 does L1 + L2
    if (b == 0) {
        if (t < 24) {
            float s = 0.0f;
            for (int k = 0; k < MEGA_NB; k++) s += __ldcg(&g_poolpart[k * 24 + t]);
            v0[t] = s;
        }
        __syncthreads();
        if (t < 96) {
            float acc = bd1[t];
#pragma unroll
            for (int i = 0; i < 24; i++) acc += v0[i] * Wd1[i * 96 + t];
            a1[t] = fmaxf(acc, 0.0f);
        }
        __syncthreads();
        {
            float acc = bd2[t];
#pragma unroll 8
            for (int i = 0; i < 96; i++) acc += a1[i] * Wd2[i * 256 + t];
            g_v1[t] = fmaxf(acc, 0.0f);
        }
    }
    gridbar(&g_barcnt, epoch, MEGA_NB);   // 2

    // phase B: L3 256->768, 12 outputs per block
    a2[t] = __ldcg(&g_v1[t]);
    __syncthreads();
    if (t < 192) {
        int jj = t >> 4, kk = t & 15;
        float acc = 0.0f;
#pragma unroll
        for (int r = 0; r < 16; r++) {
            int i = kk + 16 * r;
            acc += a2[i] * w3s[i * 12 + jj];
        }
#pragma unroll
        for (int off = 8; off >= 1; off >>= 1)
            acc += __shfl_down_sync(0xffffffffu, acc, off, 16);
        if (kk == 0) g_v2[b * 12 + jj] = fmaxf(acc + bd3s[jj], 0.0f);
    }
    gridbar(&g_barcnt, epoch, MEGA_NB);   // 3

    // phase C: L4 768->512, 8 outputs per block
#pragma unroll
    for (int k = 0; k < 3; k++) a3[t + k * 256] = __ldcg(&g_v2[t + k * 256]);
    __syncthreads();
    {
        int w = t >> 5, l = t & 31;
        float acc = 0.0f;
#pragma unroll
        for (int k = 0; k < 24; k++) {
            int i = l + 32 * k;
            acc += a3[i] * w4s[i * 8 + w];
        }
#pragma unroll
        for (int off = 16; off >= 1; off >>= 1)
            acc += __shfl_down_sync(0xffffffffu, acc, off);
        if (l == 0) g_v3[b * 8 + w] = fmaxf(acc + bd4s[w], 0.0f);
    }
    gridbar(&g_barcnt, epoch, MEGA_NB);   // 4

    // phase D: L5 -> scalar partial per block
    {
        float acc = __ldcg(&g_v3[t]) * w5s[t] + __ldcg(&g_v3[t + 256]) * w5s[t + 256];
#pragma unroll
        for (int off = 16; off >= 1; off >>= 1)
            acc += __shfl_down_sync(0xffffffffu, acc, off);
        int w = t >> 5, l = t & 31;
        if (l == 0) red8[w] = acc;
        __syncthreads();
        if (t == 0) {
            float s = 0.0f;
#pragma unroll
            for (int k = 0; k < 8; k++) s += red8[k];
            g_v3r[b] = fmaxf(s + bd5b, 0.0f) * wd6b;
        }
    }
    gridbar(&g_barcnt, epoch, MEGA_NB);   // 5

    // phase E: final
    if (b == 0 && t == 0) {
        float s = bd6[0];
#pragma unroll
        for (int k = 0; k < 64; k++) s += __ldcg(&g_v3r[k]);
        out[0] = s;
    }
}

// ---------------- launcher ----------------
extern "C" void kernel_launch(void* const* d_in, const int* in_sizes, int n_in,
                              void* d_out, int out_size)
{
    const float* x    = (const float*)d_in[0];
    const int*   ei   = (const int*)d_in[1];
    const float* e    = (const float*)d_in[2];
    const float* We1  = (const float*)d_in[3];
    const float* be1  = (const float*)d_in[4];
    const float* root1= (const float*)d_in[5];
    const float* b1   = (const float*)d_in[6];
    const float* We2  = (const float*)d_in[7];
    const float* be2  = (const float*)d_in[8];
    const float* root2= (const float*)d_in[9];
    const float* b2   = (const float*)d_in[10];
    const float* We3  = (const float*)d_in[11];
    const float* be3  = (const float*)d_in[12];
    const float* root3= (const float*)d_in[13];
    const float* b3   = (const float*)d_in[14];
    const float* Wd1  = (const float*)d_in[15];
    const float* bd1  = (const float*)d_in[16];
    const float* Wd2  = (const float*)d_in[17];
    const float* bd2  = (const float*)d_in[18];
    const float* Wd3  = (const float*)d_in[19];
    const float* bd3  = (const float*)d_in[20];
    const float* Wd4  = (const float*)d_in[21];
    const float* bd4  = (const float*)d_in[22];
    const float* Wd5  = (const float*)d_in[23];
    const float* bd5  = (const float*)d_in[24];
    const float* Wd6  = (const float*)d_in[25];
    const float* bd6  = (const float*)d_in[26];

    const int2* ei2 = (const int2*)ei;
    const float4* e4 = (const float4*)e;

    const int ntile = (N_NODES + 255) / 256;   // 79

    k_node1<<<dim3(ntile, 5), 256>>>(x, We1, be1, root1, b1);
    k_big<<<PERS_NB, 1024>>>(ei2, e4);
    k_mid<<<PERS_NB, 768>>>(We2, be2, root2, b2, We3, be3, root3, b3);
    k_mega<<<MEGA_NB, 256>>>(Wd1, bd1, Wd2, bd2, Wd3, bd3, Wd4, bd4, Wd5, bd5,
                             Wd6, bd6, (float*)d_out);
}

// round 7
// speedup vs baseline: 1.7711x; 1.7711x over previous
#include <cuda_runtime.h>
#include <cuda_bf16.h>

// ---------------- problem constants ----------------
#define N_NODES 20000
#define N_EDGES 160000
#define MEGA_NB 64

// ---------------- device scratch (static; no allocs) ----------------
__device__ __align__(16) float g_P[N_NODES * 320];   // P[n, s, o] (max 8*40 cols)
__device__ __align__(16) float g_R[N_NODES * 40];    // R[n, o]
__device__ __align__(16) float g_AGG1[N_NODES * 40];
__device__ __align__(16) float g_AGG2[N_NODES * 24];
__device__ __align__(16) float g_AGG3[N_NODES * 24];
__device__ int   g_deg[N_NODES];
__device__ int   g_cursor[N_NODES];
__device__ int   g_bsum[40];
__device__ __align__(8)  int2   g_srt[N_EDGES];        // (src, tgt) sorted by src
__device__ __align__(16) float4 g_eperm[N_EDGES * 2];  // e payload, src-sorted
__device__ float g_poolpart[MEGA_NB * 24];
__device__ __align__(16) float g_v1[256];
__device__ __align__(16) float g_v2[768];
__device__ __align__(16) float g_v3[512];
__device__ float g_v3r[64];
__device__ unsigned g_barcnt;

// ---------------- helpers ----------------
__device__ __forceinline__ void ffma2(unsigned long long& d, unsigned long long a,
                                      unsigned long long b) {
    asm("fma.rn.f32x2 %0, %1, %2, %0;" : "+l"(d) : "l"(a), "l"(b));
}
__device__ __forceinline__ unsigned long long packf2(float x) {
    unsigned long long r;
    asm("mov.b64 %0, {%1, %1};" : "=l"(r) : "f"(x));
    return r;
}
__device__ __forceinline__ float2 unpackf2(unsigned long long v) {
    float2 f;
    asm("mov.b64 {%0, %1}, %2;" : "=f"(f.x), "=f"(f.y) : "l"(v));
    return f;
}
// grid barrier for the mega kernel (MEGA_NB blocks, all resident)
__device__ __forceinline__ void gridbar(int& epoch) {
    __threadfence();
    __syncthreads();
    epoch++;
    if (threadIdx.x == 0) {
        atomicAdd(&g_barcnt, 1u);
        unsigned target = (unsigned)epoch * MEGA_NB;
        while (*((volatile unsigned*)&g_barcnt) < target) __nanosleep(20);
    }
    __syncthreads();
}

// ---------------- CSR build ----------------
__global__ void k_hist(const int2* __restrict__ ei) {
    int i = blockIdx.x * blockDim.x + threadIdx.x;
    if (i < N_EDGES) atomicAdd(&g_deg[ei[i].x], 1);
}

// two-level scan: A) per-block sums over 500-node chunks
__global__ __launch_bounds__(512) void k_scanA() {
    __shared__ int wred[16];
    int t = threadIdx.x;
    int lane = t & 31, w = t >> 5;
    int idx = blockIdx.x * 500 + t;
    int d = (t < 500 && idx < N_NODES) ? g_deg[idx] : 0;
    int s = d;
#pragma unroll
    for (int off = 16; off >= 1; off >>= 1) s += __shfl_down_sync(0xffffffffu, s, off);
    if (lane == 0) wred[w] = s;
    __syncthreads();
    if (w == 0) {
        int v = (lane < 16) ? wred[lane] : 0;
#pragma unroll
        for (int off = 8; off >= 1; off >>= 1) v += __shfl_down_sync(0xffffffffu, v, off);
        if (lane == 0) g_bsum[blockIdx.x] = v;
    }
}

// B) block-prefix + local exclusive scan -> g_cursor
__global__ __launch_bounds__(512) void k_scanB() {
    __shared__ int bs[40];
    __shared__ int base;
    __shared__ int wsum[16];
    int t = threadIdx.x;
    int lane = t & 31, w = t >> 5;
    int b = blockIdx.x;
    if (t < 40) bs[t] = g_bsum[t];
    __syncthreads();
    if (t == 0) {
        int s = 0;
#pragma unroll
        for (int i = 0; i < 40; i++) if (i < b) s += bs[i];
        base = s;
    }
    int idx = b * 500 + t;
    int d = (t < 500 && idx < N_NODES) ? g_deg[idx] : 0;
    int sc = d;
#pragma unroll
    for (int off = 1; off < 32; off <<= 1) {
        int n = __shfl_up_sync(0xffffffffu, sc, off);
        if (lane >= off) sc += n;
    }
    if (lane == 31) wsum[w] = sc;
    __syncthreads();
    if (w == 0) {
        int v = (lane < 16) ? wsum[lane] : 0;
#pragma unroll
        for (int off = 1; off < 16; off <<= 1) {
            int n = __shfl_up_sync(0xffffffffu, v, off);
            if (lane >= off) v += n;
        }
        if (lane < 16) wsum[lane] = v;
    }
    __syncthreads();
    int wbase = (w == 0) ? 0 : wsum[w - 1];
    if (t < 500 && idx < N_NODES) g_cursor[idx] = base + wbase + sc - d;
}

__global__ void k_scatter(const int2* __restrict__ ei, const float4* __restrict__ e4) {
    int i = blockIdx.x * blockDim.x + threadIdx.x;
    if (i < N_EDGES) {
        int2 st = ei[i];
        float4 a = e4[2 * i], b = e4[2 * i + 1];
        int p = atomicAdd(&g_cursor[st.x], 1);
        g_srt[p] = st;
        g_eperm[2 * p] = a;
        g_eperm[2 * p + 1] = b;
    }
}

// ---------------- node kernel ----------------
// grid (node-tiles, col-chunks); 256 thr, 1 node/thread, f32x2 math.
// cols [0,8FO): P   [8FO,9FO): R   [9FO,10FO): AGG(+bias)
// ZERO=1 (layer1): blockIdx.y==0 blocks also zero g_deg / g_barcnt.
template <int LAYER, int FI, int FO, int CC, int ZERO>
__global__ __launch_bounds__(256) void k_node(
    const float* __restrict__ xin,
    const float* __restrict__ We, const float* __restrict__ be,
    const float* __restrict__ root, const float* __restrict__ bias)
{
    constexpr int CC16 = CC * 16;
    __shared__ __align__(16) float Wsh[FI * CC16];
    __shared__ float bsh[FO];
    int t = threadIdx.x;
    int cg0 = blockIdx.y * CC;
    int colbase = cg0 * 16;

    if (ZERO) {
        if (blockIdx.y == 0) {
            int n = blockIdx.x * 256 + t;
            if (n < N_NODES) g_deg[n] = 0;
            if (blockIdx.x == 0 && t == 0) g_barcnt = 0u;
        }
    }

    for (int idx = t; idx < FI * CC16; idx += 256) {
        int f = idx / CC16, cl = idx % CC16;
        int c = colbase + cl;
        float w;
        if (c < 8 * FO) {
            int s = c / FO, o = c % FO;
            w = We[s * (FI * FO) + f * FO + o];
        } else if (c < 9 * FO) {
            int o = c - 8 * FO;
            w = be[f * FO + o];
        } else {
            int o = c - 9 * FO;
            w = root[f * FO + o];
        }
        Wsh[idx] = w;
    }
    for (int idx = t; idx < FO; idx += 256) bsh[idx] = bias[idx];
    __syncthreads();

    int node = blockIdx.x * 256 + t;
    if (node >= N_NODES) return;

    const float* hin;
    if (LAYER == 1)      hin = xin;
    else if (LAYER == 2) hin = g_AGG1;
    else                 hin = g_AGG2;
    float* AGG;
    if (LAYER == 1)      AGG = g_AGG1;
    else if (LAYER == 2) AGG = g_AGG2;
    else                 AGG = g_AGG3;

    float h[FI];
    const float4* hv = reinterpret_cast<const float4*>(hin + (size_t)node * FI);
#pragma unroll
    for (int f4 = 0; f4 < FI / 4; f4++) {
        float4 a = hv[f4];
        if (LAYER != 1) {
            a.x = fmaxf(a.x, 0.f); a.y = fmaxf(a.y, 0.f);
            a.z = fmaxf(a.z, 0.f); a.w = fmaxf(a.w, 0.f);
        }
        h[4*f4+0]=a.x; h[4*f4+1]=a.y; h[4*f4+2]=a.z; h[4*f4+3]=a.w;
    }

    const ulonglong2* Wv = reinterpret_cast<const ulonglong2*>(Wsh);
    float4* Pv = reinterpret_cast<float4*>(g_P) + (size_t)node * (8 * FO / 4);
    float4* Rv = reinterpret_cast<float4*>(g_R) + (size_t)node * (FO / 4);
    float4* Av = reinterpret_cast<float4*>(AGG) + (size_t)node * (FO / 4);

#pragma unroll
    for (int cg = 0; cg < CC; cg++) {
        unsigned long long acc[8];
#pragma unroll
        for (int k = 0; k < 8; k++) acc[k] = 0ull;
#pragma unroll
        for (int f = 0; f < FI; f++) {
            const ulonglong2* wrow = Wv + f * (CC * 4) + cg * 4;
            ulonglong2 wA = wrow[0], wB = wrow[1], wC = wrow[2], wD = wrow[3];
            unsigned long long ha = packf2(h[f]);
            ffma2(acc[0], ha, wA.x); ffma2(acc[1], ha, wA.y);
            ffma2(acc[2], ha, wB.x); ffma2(acc[3], ha, wB.y);
            ffma2(acc[4], ha, wC.x); ffma2(acc[5], ha, wC.y);
            ffma2(acc[6], ha, wD.x); ffma2(acc[7], ha, wD.y);
        }
#pragma unroll
        for (int q = 0; q < 4; q++) {
            int cb = (cg0 + cg) * 16 + q * 4;
            float2 a0 = unpackf2(acc[2*q]), a1 = unpackf2(acc[2*q+1]);
            float4 va = make_float4(a0.x, a0.y, a1.x, a1.y);
            if (cb < 8 * FO) {
                Pv[cb / 4] = va;
            } else if (cb < 9 * FO) {
                Rv[(cb - 8 * FO) / 4] = va;
            } else {
                int o = cb - 9 * FO;
                va.x += bsh[o]; va.y += bsh[o+1]; va.z += bsh[o+2]; va.w += bsh[o+3];
                Av[o / 4] = va;
            }
        }
    }
}

// ---------------- edge kernel ----------------
// TPE threads per edge, each handles FO4/TPE float4 column chunks.
// Shorter per-thread chains + more warps to hide L2/REDG latency.
template <int LAYER, int FO, int TPE>
__global__ __launch_bounds__(256) void k_edge()
{
    constexpr int FO4 = FO / 4;
    constexpr int CH = FO4 / TPE;   // chunks per thread
    int gid = blockIdx.x * 256 + threadIdx.x;
    int edge = gid / TPE;
    if (edge >= N_EDGES) return;
    int part = gid - edge * TPE;

    int2 st = g_srt[edge];
    float4 ea = g_eperm[2 * edge];
    float4 eb = g_eperm[2 * edge + 1];

    const float4* P = reinterpret_cast<const float4*>(g_P)
                      + (size_t)st.x * (8 * FO4) + part * CH;
    const float4* R = reinterpret_cast<const float4*>(g_R)
                      + (size_t)st.x * FO4 + part * CH;
    float* AGG;
    if (LAYER == 1)      AGG = g_AGG1;
    else if (LAYER == 2) AGG = g_AGG2;
    else                 AGG = g_AGG3;
    float* dst = AGG + (size_t)st.y * FO + part * CH * 4;

#pragma unroll
    for (int c = 0; c < CH; c++) {
        float4 m = R[c];
        float4 p;
#define ACC_TERM(ES, SI) { p = P[(SI) * FO4 + c]; \
        m.x += (ES) * p.x; m.y += (ES) * p.y; m.z += (ES) * p.z; m.w += (ES) * p.w; }
        ACC_TERM(ea.x, 0) ACC_TERM(ea.y, 1) ACC_TERM(ea.z, 2) ACC_TERM(ea.w, 3)
        ACC_TERM(eb.x, 4) ACC_TERM(eb.y, 5) ACC_TERM(eb.z, 6) ACC_TERM(eb.w, 7)
#undef ACC_TERM
        asm volatile("red.global.add.v4.f32 [%0], {%1,%2,%3,%4};"
                     :: "l"(dst + c * 4), "f"(m.x), "f"(m.y), "f"(m.z), "f"(m.w)
                     : "memory");
    }
}

// ---------------- mega kernel: pool + whole MLP (64 x 512) ----------------
__global__ __launch_bounds__(512) void k_mega(
    const float* __restrict__ Wd1, const float* __restrict__ bd1,
    const float* __restrict__ Wd2, const float* __restrict__ bd2,
    const float* __restrict__ Wd3, const float* __restrict__ bd3,
    const float* __restrict__ Wd4, const float* __restrict__ bd4,
    const float* __restrict__ Wd5, const float* __restrict__ bd5,
    const float* __restrict__ Wd6, const float* __restrict__ bd6,
    float* __restrict__ out)
{
    __shared__ float w3s[256 * 12];
    __shared__ float w4s[768 * 8];
    __shared__ float w5s[512];
    __shared__ float a2[256];
    __shared__ float a3[768];
    __shared__ float v0[24];
    __shared__ float a1[96];
    __shared__ float poolacc[21][24];
    __shared__ float bd3s[12], bd4s[8];
    __shared__ float red8[8];

    int t = threadIdx.x;
    int b = blockIdx.x;
    int epoch = 0;

    // weight staging (harness inputs)
    for (int idx = t; idx < 256 * 12; idx += 512) {
        int i = idx / 12, j = idx % 12;
        w3s[idx] = Wd3[i * 768 + b * 12 + j];
    }
    for (int idx = t; idx < 768 * 8; idx += 512) {
        int i = idx / 8, j = idx % 8;
        w4s[idx] = Wd4[i * 512 + b * 8 + j];
    }
    if (t < 512) w5s[t] = Wd5[t * 64 + b];
    if (t < 12) bd3s[t] = bd3[b * 12 + t];
    if (t < 8)  bd4s[t] = bd4[b * 8 + t];
    float bd5b = bd5[b];
    float wd6b = Wd6[b];

    // phase P: pool partials (21 row-slots per block)
    {
        int c = t % 24, slot = t / 24;
        if (slot < 21) {
            float local = 0.0f;
            for (int r = b * 21 + slot; r < N_NODES; r += MEGA_NB * 21)
                local += fmaxf(__ldcg(&g_AGG3[r * 24 + c]), 0.0f);
            poolacc[slot][c] = local;
        }
        __syncthreads();
        if (t < 24) {
            float s = 0.0f;
#pragma unroll
            for (int k = 0; k < 21; k++) s += poolacc[k][t];
            g_poolpart[b * 24 + t] = s;
        }
    }
    gridbar(epoch);   // 1

    // phase A: block 0 does L1 (24->96) + L2 (96->256)
    if (b == 0) {
        if (t < 24) {
            float s = 0.0f;
            for (int k = 0; k < MEGA_NB; k++) s += __ldcg(&g_poolpart[k * 24 + t]);
            v0[t] = s;
        }
        __syncthreads();
        if (t < 96) {
            float acc = bd1[t];
#pragma unroll
            for (int i = 0; i < 24; i++) acc += v0[i] * Wd1[i * 96 + t];
            a1[t] = fmaxf(acc, 0.0f);
        }
        __syncthreads();
        if (t < 256) {
            float acc = bd2[t];
#pragma unroll 8
            for (int i = 0; i < 96; i++) acc += a1[i] * Wd2[i * 256 + t];
            g_v1[t] = fmaxf(acc, 0.0f);
        }
    }
    gridbar(epoch);   // 2

    // phase B: L3 256->768, 12 outputs per block (16 threads each; warps 0-5)
    if (t < 256) a2[t] = __ldcg(&g_v1[t]);
    __syncthreads();
    if (t < 192) {
        int jj = t >> 4, kk = t & 15;
        float acc = 0.0f;
#pragma unroll
        for (int r = 0; r < 16; r++) {
            int i = kk + 16 * r;
            acc += a2[i] * w3s[i * 12 + jj];
        }
#pragma unroll
        for (int off = 8; off >= 1; off >>= 1)
            acc += __shfl_down_sync(0xffffffffu, acc, off, 16);
        if (kk == 0) g_v2[b * 12 + jj] = fmaxf(acc + bd3s[jj], 0.0f);
    }
    gridbar(epoch);   // 3

    // phase C: L4 768->512, 8 outputs per block (warps 0-7)
    if (t < 256) {
#pragma unroll
        for (int k = 0; k < 3; k++) a3[t + k * 256] = __ldcg(&g_v2[t + k * 256]);
    }
    __syncthreads();
    if (t < 256) {
        int w = t >> 5, l = t & 31;
        float acc = 0.0f;
#pragma unroll
        for (int k = 0; k < 24; k++) {
            int i = l + 32 * k;
            acc += a3[i] * w4s[i * 8 + w];
        }
#pragma unroll
        for (int off = 16; off >= 1; off >>= 1)
            acc += __shfl_down_sync(0xffffffffu, acc, off);
        if (l == 0) g_v3[b * 8 + w] = fmaxf(acc + bd4s[w], 0.0f);
    }
    gridbar(epoch);   // 4

    // phase D: L5 512->64 (output b) * W6[b]  (warps 0-7)
    if (t < 256) {
        float acc = __ldcg(&g_v3[t]) * w5s[t] + __ldcg(&g_v3[t + 256]) * w5s[t + 256];
#pragma unroll
        for (int off = 16; off >= 1; off >>= 1)
            acc += __shfl_down_sync(0xffffffffu, acc, off);
        int w = t >> 5, l = t & 31;
        if (l == 0) red8[w] = acc;
    }
    __syncthreads();
    if (t == 0) {
        float s = 0.0f;
#pragma unroll
        for (int k = 0; k < 8; k++) s += red8[k];
        g_v3r[b] = fmaxf(s + bd5b, 0.0f) * wd6b;
    }
    gridbar(epoch);   // 5

    // phase E: block 0 final
    if (b == 0 && t == 0) {
        float s = bd6[0];
#pragma unroll
        for (int k = 0; k < 64; k++) s += __ldcg(&g_v3r[k]);
        out[0] = s;
    }
}

// ---------------- launcher ----------------
extern "C" void kernel_launch(void* const* d_in, const int* in_sizes, int n_in,
                              void* d_out, int out_size)
{
    const float* x    = (const float*)d_in[0];
    const int*   ei   = (const int*)d_in[1];
    const float* e    = (const float*)d_in[2];
    const float* We1  = (const float*)d_in[3];
    const float* be1  = (const float*)d_in[4];
    const float* root1= (const float*)d_in[5];
    const float* b1   = (const float*)d_in[6];
    const float* We2  = (const float*)d_in[7];
    const float* be2  = (const float*)d_in[8];
    const float* root2= (const float*)d_in[9];
    const float* b2   = (const float*)d_in[10];
    const float* We3  = (const float*)d_in[11];
    const float* be3  = (const float*)d_in[12];
    const float* root3= (const float*)d_in[13];
    const float* b3   = (const float*)d_in[14];
    const float* Wd1  = (const float*)d_in[15];
    const float* bd1  = (const float*)d_in[16];
    const float* Wd2  = (const float*)d_in[17];
    const float* bd2  = (const float*)d_in[18];
    const float* Wd3  = (const float*)d_in[19];
    const float* bd3  = (const float*)d_in[20];
    const float* Wd4  = (const float*)d_in[21];
    const float* bd4  = (const float*)d_in[22];
    const float* Wd5  = (const float*)d_in[23];
    const float* bd5  = (const float*)d_in[24];
    const float* Wd6  = (const float*)d_in[25];
    const float* bd6  = (const float*)d_in[26];

    const int2* ei2 = (const int2*)ei;
    const float4* e4 = (const float4*)e;

    const int ntile = (N_NODES + 255) / 256;                 // 79
    const int flat_grid = (N_EDGES + 255) / 256;             // 625
    const int edge_grid40 = (5 * N_EDGES + 255) / 256;       // 3125
    const int edge_grid24 = (3 * N_EDGES + 255) / 256;       // 1875

    // node1 also zeroes g_deg / g_barcnt (independent of CSR)
    k_node<1, 16, 40, 5, 1><<<dim3(ntile, 5), 256>>>(x, We1, be1, root1, b1);
    k_hist<<<flat_grid, 256>>>(ei2);
    k_scanA<<<40, 512>>>();
    k_scanB<<<40, 512>>>();
    k_scatter<<<flat_grid, 256>>>(ei2, e4);
    k_edge<1, 40, 5><<<edge_grid40, 256>>>();
    k_node<2, 40, 24, 5, 0><<<dim3(ntile, 3), 256>>>(nullptr, We2, be2, root2, b2);
    k_edge<2, 24, 3><<<edge_grid24, 256>>>();
    k_node<3, 24, 24, 5, 0><<<dim3(ntile, 3), 256>>>(nullptr, We3, be3, root3, b3);
    k_edge<3, 24, 3><<<edge_grid24, 256>>>();
    k_mega<<<MEGA_NB, 512>>>(Wd1, bd1, Wd2, bd2, Wd3, bd3, Wd4, bd4, Wd5, bd5,
                             Wd6, bd6, (float*)d_out);
}